// round 1
// baseline (speedup 1.0000x reference)
#include <cuda_runtime.h>
#include <cuda_bf16.h>

#define NN 100000
#define NE 1600000
#define ET 1700000   // NE + NN self loops
#define HID 64
#define INCH 256
#define NEG_SLOPE 0.2f

// ---------------- scratch (device globals; no allocation allowed) ----------------
__device__ float    g_h[NN * HID];    // pre-attention features of current layer
__device__ float    g_out[NN * HID];  // unnormalized attention accumulator
__device__ float    g_hl[NN * HID];   // layer-1 output (layer-2 input)
__device__ float    g_as[NN];
__device__ float    g_ad[NN];
__device__ unsigned g_max[NN];        // order-flipped float for atomicMax
__device__ float    g_den[NN];
__device__ float    g_w[ET];

// order-preserving float<->uint for atomicMax
__device__ __forceinline__ unsigned fflip(float f) {
    unsigned u = __float_as_uint(f);
    return (u & 0x80000000u) ? ~u : (u | 0x80000000u);
}
__device__ __forceinline__ float funflip(unsigned u) {
    return (u & 0x80000000u) ? __uint_as_float(u & 0x7fffffffu) : __uint_as_float(~u);
}

// ---------------- init: zero accumulators ----------------
__global__ void init_kernel() {
    int i = blockIdx.x * blockDim.x + threadIdx.x;
    if (i < NN * HID) g_out[i] = 0.0f;
    if (i < NN) { g_den[i] = 0.0f; g_max[i] = 0u; }  // 0 == flip(-inf)
}

// ---------------- GEMM layer 1: g_h = x @ W1, g_as/g_ad fused ----------------
__global__ void gemm1_kernel(const float* __restrict__ x, const float* __restrict__ W,
                             const float* __restrict__ a_s, const float* __restrict__ a_d) {
    __shared__ float sx[8][INCH];
    int warp = threadIdx.x >> 5;
    int lane = threadIdx.x & 31;
    int row = blockIdx.x * 8 + warp;
    if (row >= NN) return;

    const float4* xr = (const float4*)(x + (size_t)row * INCH);
    ((float4*)sx[warp])[lane]      = xr[lane];
    ((float4*)sx[warp])[lane + 32] = xr[lane + 32];
    __syncwarp();

    float accx = 0.0f, accy = 0.0f;
    #pragma unroll 8
    for (int k = 0; k < INCH; k++) {
        float xv = sx[warp][k];
        float2 wv = ((const float2*)(W + k * HID))[lane];
        accx = fmaf(xv, wv.x, accx);
        accy = fmaf(xv, wv.y, accy);
    }
    int c0 = 2 * lane;
    *(float2*)(g_h + (size_t)row * HID + c0) = make_float2(accx, accy);

    float ps = accx * a_s[c0] + accy * a_s[c0 + 1];
    float pd = accx * a_d[c0] + accy * a_d[c0 + 1];
    #pragma unroll
    for (int o = 16; o; o >>= 1) {
        ps += __shfl_down_sync(0xffffffffu, ps, o);
        pd += __shfl_down_sync(0xffffffffu, pd, o);
    }
    if (lane == 0) { g_as[row] = ps; g_ad[row] = pd; }
}

// ---------------- GEMM layer 2: g_h = g_hl @ W2, scores fused ----------------
__global__ void gemm2_kernel(const float* __restrict__ W,
                             const float* __restrict__ a_s, const float* __restrict__ a_d) {
    __shared__ float sx[8][HID];
    int warp = threadIdx.x >> 5;
    int lane = threadIdx.x & 31;
    int row = blockIdx.x * 8 + warp;
    if (row >= NN) return;

    ((float2*)sx[warp])[lane] = ((const float2*)(g_hl + (size_t)row * HID))[lane];
    __syncwarp();

    float accx = 0.0f, accy = 0.0f;
    #pragma unroll 8
    for (int k = 0; k < HID; k++) {
        float xv = sx[warp][k];
        float2 wv = ((const float2*)(W + k * HID))[lane];
        accx = fmaf(xv, wv.x, accx);
        accy = fmaf(xv, wv.y, accy);
    }
    int c0 = 2 * lane;
    *(float2*)(g_h + (size_t)row * HID + c0) = make_float2(accx, accy);

    float ps = accx * a_s[c0] + accy * a_s[c0 + 1];
    float pd = accx * a_d[c0] + accy * a_d[c0 + 1];
    #pragma unroll
    for (int o = 16; o; o >>= 1) {
        ps += __shfl_down_sync(0xffffffffu, ps, o);
        pd += __shfl_down_sync(0xffffffffu, pd, o);
    }
    if (lane == 0) { g_as[row] = ps; g_ad[row] = pd; }
}

// ---------------- per-edge leaky-relu score -> segment max ----------------
__global__ void edge_max_kernel(const int* __restrict__ ei) {
    int e = blockIdx.x * blockDim.x + threadIdx.x;
    if (e >= ET) return;
    int s, d;
    if (e < NE) { s = ei[e]; d = ei[NE + e]; } else { s = d = e - NE; }
    float v = g_as[s] + g_ad[d];
    v = (v > 0.0f) ? v : NEG_SLOPE * v;
    atomicMax(&g_max[d], fflip(v));
}

// ---------------- w = exp(e - m[dst]); segment sum ----------------
__global__ void edge_sum_kernel(const int* __restrict__ ei) {
    int e = blockIdx.x * blockDim.x + threadIdx.x;
    if (e >= ET) return;
    int s, d;
    if (e < NE) { s = ei[e]; d = ei[NE + e]; } else { s = d = e - NE; }
    float v = g_as[s] + g_ad[d];
    v = (v > 0.0f) ? v : NEG_SLOPE * v;
    float w = __expf(v - funflip(g_max[d]));
    g_w[e] = w;
    atomicAdd(&g_den[d], w);
}

// ---------------- scatter: g_out[dst] += w * g_h[src]  (16 lanes/edge, vec4 red) -----
__global__ void scatter_kernel(const int* __restrict__ ei) {
    int t = blockIdx.x * blockDim.x + threadIdx.x;
    int e = t >> 4;
    int l = t & 15;
    if (e >= ET) return;
    int s, d;
    if (e < NE) { s = ei[e]; d = ei[NE + e]; } else { s = d = e - NE; }
    float w = g_w[e];
    float4 hv = *(const float4*)(g_h + (size_t)s * HID + l * 4);
    float4 val = make_float4(hv.x * w, hv.y * w, hv.z * w, hv.w * w);
    atomicAdd((float4*)(g_out + (size_t)d * HID + l * 4), val);
}

// ---------------- layer-1 epilogue: normalize + bias + relu -> g_hl ----------------
__global__ void epi1_kernel(const float* __restrict__ b) {
    int i = blockIdx.x * blockDim.x + threadIdx.x;
    if (i >= NN * HID) return;
    int n = i >> 6;
    int c = i & 63;
    float v = g_out[i] / g_den[n] + b[c];
    g_hl[i] = (v > 0.0f) ? v : 0.0f;
}

// ---------------- layer-2 epilogue + both heads (warp per node) ----------------
__global__ void epi2_heads_kernel(const float* __restrict__ b2,
                                  const float* __restrict__ Wf, const float* __restrict__ bf,
                                  const float* __restrict__ Ws, const float* __restrict__ bs,
                                  float* __restrict__ out) {
    int gwarp = (blockIdx.x * blockDim.x + threadIdx.x) >> 5;
    int lane = threadIdx.x & 31;
    if (gwarp >= NN) return;

    float inv = 1.0f / g_den[gwarp];
    int c0 = 2 * lane;
    float2 o = *(const float2*)(g_out + (size_t)gwarp * HID + c0);
    float h0 = o.x * inv + b2[c0];
    float h1 = o.y * inv + b2[c0 + 1];
    h0 = (h0 > 0.0f) ? h0 : 0.0f;
    h1 = (h1 > 0.0f) ? h1 : 0.0f;

    float acc[10];
    #pragma unroll
    for (int j = 0; j < 3; j++)
        acc[j] = h0 * Wf[c0 * 3 + j] + h1 * Wf[(c0 + 1) * 3 + j];
    #pragma unroll
    for (int j = 0; j < 7; j++)
        acc[3 + j] = h0 * Ws[c0 * 7 + j] + h1 * Ws[(c0 + 1) * 7 + j];

    #pragma unroll
    for (int j = 0; j < 10; j++) {
        #pragma unroll
        for (int o2 = 16; o2; o2 >>= 1)
            acc[j] += __shfl_down_sync(0xffffffffu, acc[j], o2);
    }
    if (lane == 0) {
        #pragma unroll
        for (int j = 0; j < 3; j++) out[(size_t)gwarp * 3 + j] = acc[j] + bf[j];
        #pragma unroll
        for (int j = 0; j < 7; j++) out[(size_t)NN * 3 + (size_t)gwarp * 7 + j] = acc[3 + j] + bs[j];
    }
}

extern "C" void kernel_launch(void* const* d_in, const int* in_sizes, int n_in,
                              void* d_out, int out_size) {
    const float* x    = (const float*)d_in[0];
    const int*   ei   = (const int*)d_in[1];
    const float* W1   = (const float*)d_in[2];
    const float* as1  = (const float*)d_in[3];
    const float* ad1  = (const float*)d_in[4];
    const float* b1   = (const float*)d_in[5];
    const float* W2   = (const float*)d_in[6];
    const float* as2  = (const float*)d_in[7];
    const float* ad2  = (const float*)d_in[8];
    const float* b2   = (const float*)d_in[9];
    const float* Wf   = (const float*)d_in[10];
    const float* bf   = (const float*)d_in[11];
    const float* Ws   = (const float*)d_in[12];
    const float* bs   = (const float*)d_in[13];
    float* out = (float*)d_out;

    const int TB = 256;
    dim3 gInit((NN * HID + TB - 1) / TB);
    dim3 gRows((NN + 7) / 8);
    dim3 gEdge((ET + TB - 1) / TB);
    dim3 gScat(((size_t)ET * 16 + TB - 1) / TB);
    dim3 gElem((NN * HID + TB - 1) / TB);
    dim3 gNodeWarp(((size_t)NN * 32 + TB - 1) / TB);

    // ---- layer 1 ----
    init_kernel<<<gInit, TB>>>();
    gemm1_kernel<<<gRows, TB>>>(x, W1, as1, ad1);
    edge_max_kernel<<<gEdge, TB>>>(ei);
    edge_sum_kernel<<<gEdge, TB>>>(ei);
    scatter_kernel<<<gScat, TB>>>(ei);
    epi1_kernel<<<gElem, TB>>>(b1);

    // ---- layer 2 ----
    init_kernel<<<gInit, TB>>>();
    gemm2_kernel<<<gRows, TB>>>(W2, as2, ad2);
    edge_max_kernel<<<gEdge, TB>>>(ei);
    edge_sum_kernel<<<gEdge, TB>>>(ei);
    scatter_kernel<<<gScat, TB>>>(ei);
    epi2_heads_kernel<<<gNodeWarp, TB>>>(b2, Wf, bf, Ws, bs, out);
}

// round 2
// speedup vs baseline: 1.9659x; 1.9659x over previous
#include <cuda_runtime.h>
#include <cuda_bf16.h>

#define NN 100000
#define NE 1600000
#define HID 64
#define NEG_SLOPE 0.2f
#define NB_SCAN 98          // ceil(NN/1024)

// ---------------- scratch (device globals) ----------------
__device__ float g_h[NN * HID];     // pre-attention features of current layer
__device__ float g_hl[NN * HID];    // layer-1 output (layer-2 input)
__device__ float g_as[NN];
__device__ float g_ad[NN];
__device__ int   g_cnt[NN];
__device__ int   g_cur[NN];
__device__ int   g_rowptr[NN + 1];
__device__ int   g_bsum[NB_SCAN];
__device__ int   g_csr[NE];

// ---------------- f32x2 helpers ----------------
__device__ __forceinline__ unsigned long long ffma2(unsigned long long a,
                                                    unsigned long long b,
                                                    unsigned long long c) {
    unsigned long long d;
    asm("fma.rn.f32x2 %0,%1,%2,%3;" : "=l"(d) : "l"(a), "l"(b), "l"(c));
    return d;
}
__device__ __forceinline__ unsigned long long dup2(float x) {
    unsigned long long r;
    asm("mov.b64 %0,{%1,%1};" : "=l"(r) : "f"(x));
    return r;
}
__device__ __forceinline__ float2 unpk(unsigned long long p) {
    float2 r;
    asm("mov.b64 {%0,%1},%2;" : "=f"(r.x), "=f"(r.y) : "l"(p));
    return r;
}
__device__ __forceinline__ float lrelu(float v) {
    return (v > 0.0f) ? v : NEG_SLOPE * v;
}

// ================= CSR build =================
__global__ void zero_kernel() {
    int i = blockIdx.x * blockDim.x + threadIdx.x;
    if (i < NN) { g_cnt[i] = 0; g_cur[i] = 0; }
}
__global__ void hist_kernel(const int* __restrict__ ei) {
    int e = blockIdx.x * blockDim.x + threadIdx.x;
    if (e >= NE) return;
    atomicAdd(&g_cnt[ei[NE + e]], 1);
}
__global__ void scan1_kernel() {
    __shared__ int s[1024];
    int i = blockIdx.x * 1024 + threadIdx.x;
    int v = (i < NN) ? g_cnt[i] : 0;
    s[threadIdx.x] = v;
    __syncthreads();
    #pragma unroll
    for (int o = 1; o < 1024; o <<= 1) {
        int t = (threadIdx.x >= o) ? s[threadIdx.x - o] : 0;
        __syncthreads();
        s[threadIdx.x] += t;
        __syncthreads();
    }
    if (i < NN) g_rowptr[i] = s[threadIdx.x] - v;   // exclusive
    if (threadIdx.x == 1023) g_bsum[blockIdx.x] = s[1023];
}
__global__ void scan2_kernel() {
    if (threadIdx.x == 0) {
        int acc = 0;
        for (int b = 0; b < NB_SCAN; b++) { int t = g_bsum[b]; g_bsum[b] = acc; acc += t; }
        g_rowptr[NN] = acc;   // == NE
    }
}
__global__ void scan3_kernel() {
    int i = blockIdx.x * blockDim.x + threadIdx.x;
    if (i < NN) g_rowptr[i] += g_bsum[i >> 10];
}
__global__ void fill_kernel(const int* __restrict__ ei) {
    int e = blockIdx.x * blockDim.x + threadIdx.x;
    if (e >= NE) return;
    int s = ei[e], d = ei[NE + e];
    int pos = g_rowptr[d] + atomicAdd(&g_cur[d], 1);
    g_csr[pos] = s;
}

// ================= tiled GEMM (128 rows x 64 cols per block, FFMA2) =================
template<int K>
__global__ void __launch_bounds__(256) gemm_kernel(const float* __restrict__ X,
                                                   const float* __restrict__ W,
                                                   float* __restrict__ H, int nrows) {
    __shared__ float xs[16][132];   // transposed x chunk: xs[kk][row]
    __shared__ float ws[16][64];    // w chunk: ws[kk][col]
    int t = threadIdx.x;
    int rowblk = blockIdx.x * 128;

    int col4 = (t & 15) * 4;        // 4 consecutive output cols
    int r0   = (t >> 4) * 8;        // 8 consecutive rows (4 packed pairs)

    unsigned long long acc[4][4];
    #pragma unroll
    for (int i = 0; i < 4; i++)
        #pragma unroll
        for (int j = 0; j < 4; j++) acc[i][j] = 0ull;

    // x load mapping: thread pair covers one row's 16-k chunk (coalesced 32B/thr-pair)
    int lrow = t >> 1;
    int lk   = (t & 1) * 8;
    int grow = rowblk + lrow; if (grow >= nrows) grow = nrows - 1;
    const float4* xsrc = (const float4*)(X + (size_t)grow * K);

    for (int k0 = 0; k0 < K; k0 += 16) {
        float4 v0 = xsrc[(k0 + lk) >> 2];
        float4 v1 = xsrc[(k0 + lk + 4) >> 2];
        float4 wv4 = ((const float4*)(W + k0 * 64))[t];
        __syncthreads();
        xs[lk + 0][lrow] = v0.x; xs[lk + 1][lrow] = v0.y;
        xs[lk + 2][lrow] = v0.z; xs[lk + 3][lrow] = v0.w;
        xs[lk + 4][lrow] = v1.x; xs[lk + 5][lrow] = v1.y;
        xs[lk + 6][lrow] = v1.z; xs[lk + 7][lrow] = v1.w;
        ((float4*)ws)[t] = wv4;
        __syncthreads();
        #pragma unroll
        for (int kk = 0; kk < 16; kk++) {
            float4 wv = *(const float4*)&ws[kk][col4];
            unsigned long long wd0 = dup2(wv.x), wd1 = dup2(wv.y),
                               wd2 = dup2(wv.z), wd3 = dup2(wv.w);
            #pragma unroll
            for (int i = 0; i < 4; i++) {
                unsigned long long xp =
                    *(const unsigned long long*)&xs[kk][r0 + 2 * i];
                acc[i][0] = ffma2(xp, wd0, acc[i][0]);
                acc[i][1] = ffma2(xp, wd1, acc[i][1]);
                acc[i][2] = ffma2(xp, wd2, acc[i][2]);
                acc[i][3] = ffma2(xp, wd3, acc[i][3]);
            }
        }
    }
    int orow = rowblk + r0;
    #pragma unroll
    for (int i = 0; i < 4; i++) {
        float2 c0 = unpk(acc[i][0]), c1 = unpk(acc[i][1]),
               c2 = unpk(acc[i][2]), c3 = unpk(acc[i][3]);
        int rlo = orow + 2 * i, rhi = rlo + 1;
        if (rlo < nrows)
            *(float4*)(H + (size_t)rlo * 64 + col4) = make_float4(c0.x, c1.x, c2.x, c3.x);
        if (rhi < nrows)
            *(float4*)(H + (size_t)rhi * 64 + col4) = make_float4(c0.y, c1.y, c2.y, c3.y);
    }
}

// ================= per-node attention scores =================
__global__ void scores_kernel(const float* __restrict__ h,
                              const float* __restrict__ a_s,
                              const float* __restrict__ a_d) {
    int r = (blockIdx.x * blockDim.x + threadIdx.x) >> 5;
    int lane = threadIdx.x & 31;
    if (r >= NN) return;
    float2 hv = ((const float2*)(h + (size_t)r * HID))[lane];
    int c0 = 2 * lane;
    float ps = hv.x * a_s[c0] + hv.y * a_s[c0 + 1];
    float pd = hv.x * a_d[c0] + hv.y * a_d[c0 + 1];
    #pragma unroll
    for (int o = 16; o; o >>= 1) {
        ps += __shfl_down_sync(0xffffffffu, ps, o);
        pd += __shfl_down_sync(0xffffffffu, pd, o);
    }
    if (lane == 0) { g_as[r] = ps; g_ad[r] = pd; }
}

// ================= fused aggregation: softmax + weighted gather + epilogue ===========
template<bool LAYER2>
__global__ void aggregate_kernel(const float* __restrict__ h,
                                 const float* __restrict__ bias,
                                 float* __restrict__ dsth,          // layer1 output
                                 const float* __restrict__ Wf, const float* __restrict__ bf,
                                 const float* __restrict__ Ws, const float* __restrict__ bs,
                                 float* __restrict__ out) {
    int n = (blockIdx.x * blockDim.x + threadIdx.x) >> 5;
    int lane = threadIdx.x & 31;
    if (n >= NN) return;
    int base = g_rowptr[n], end = g_rowptr[n + 1];
    float adn = g_ad[n];
    float eself = lrelu(g_as[n] + adn);

    // pass 1: segment max (lanes strided over edges)
    float m = eself;
    for (int j = base + lane; j < end; j += 32)
        m = fmaxf(m, lrelu(g_as[g_csr[j]] + adn));
    #pragma unroll
    for (int o = 16; o; o >>= 1)
        m = fmaxf(m, __shfl_xor_sync(0xffffffffu, m, o));

    // pass 2: exp-weighted gather (serial over edges, lanes = 2 feature cols)
    int c0 = 2 * lane;
    float wself = __expf(eself - m);
    float den = wself;
    float2 hv = *(const float2*)(h + (size_t)n * HID + c0);
    float accx = wself * hv.x, accy = wself * hv.y;

    int src0 = (base < end) ? g_csr[base] : 0;
    float a0 = (base < end) ? g_as[src0] : 0.0f;
    for (int j = base; j < end; j++) {
        int src1 = 0; float a1 = 0.0f;
        if (j + 1 < end) { src1 = g_csr[j + 1]; a1 = g_as[src1]; }
        float w = __expf(lrelu(a0 + adn) - m);
        den += w;
        float2 hs = *(const float2*)(h + (size_t)src0 * HID + c0);
        accx = fmaf(w, hs.x, accx);
        accy = fmaf(w, hs.y, accy);
        src0 = src1; a0 = a1;
    }

    float inv = 1.0f / den;
    float h0 = accx * inv + bias[c0];
    float h1 = accy * inv + bias[c0 + 1];
    h0 = (h0 > 0.0f) ? h0 : 0.0f;
    h1 = (h1 > 0.0f) ? h1 : 0.0f;

    if (!LAYER2) {
        *(float2*)(dsth + (size_t)n * HID + c0) = make_float2(h0, h1);
    } else {
        float acc[10];
        #pragma unroll
        for (int j = 0; j < 3; j++)
            acc[j] = h0 * Wf[c0 * 3 + j] + h1 * Wf[(c0 + 1) * 3 + j];
        #pragma unroll
        for (int j = 0; j < 7; j++)
            acc[3 + j] = h0 * Ws[c0 * 7 + j] + h1 * Ws[(c0 + 1) * 7 + j];
        #pragma unroll
        for (int j = 0; j < 10; j++) {
            #pragma unroll
            for (int o = 16; o; o >>= 1)
                acc[j] += __shfl_down_sync(0xffffffffu, acc[j], o);
        }
        if (lane == 0) {
            #pragma unroll
            for (int j = 0; j < 3; j++) out[(size_t)n * 3 + j] = acc[j] + bf[j];
            #pragma unroll
            for (int j = 0; j < 7; j++)
                out[(size_t)NN * 3 + (size_t)n * 7 + j] = acc[3 + j] + bs[j];
        }
    }
}

extern "C" void kernel_launch(void* const* d_in, const int* in_sizes, int n_in,
                              void* d_out, int out_size) {
    const float* x    = (const float*)d_in[0];
    const int*   ei   = (const int*)d_in[1];
    const float* W1   = (const float*)d_in[2];
    const float* as1  = (const float*)d_in[3];
    const float* ad1  = (const float*)d_in[4];
    const float* b1   = (const float*)d_in[5];
    const float* W2   = (const float*)d_in[6];
    const float* as2  = (const float*)d_in[7];
    const float* ad2  = (const float*)d_in[8];
    const float* b2   = (const float*)d_in[9];
    const float* Wf   = (const float*)d_in[10];
    const float* bf   = (const float*)d_in[11];
    const float* Ws   = (const float*)d_in[12];
    const float* bs   = (const float*)d_in[13];
    float* out = (float*)d_out;

    float* d_gh;  cudaGetSymbolAddress((void**)&d_gh,  g_h);
    float* d_ghl; cudaGetSymbolAddress((void**)&d_ghl, g_hl);

    const int TB = 256;
    dim3 gNode((NN + TB - 1) / TB);
    dim3 gEdge((NE + TB - 1) / TB);
    dim3 gGemm((NN + 127) / 128);
    dim3 gWarpNode(((size_t)NN * 32 + TB - 1) / TB);

    // ---- CSR build (shared by both layers) ----
    zero_kernel<<<gNode, TB>>>();
    hist_kernel<<<gEdge, TB>>>(ei);
    scan1_kernel<<<NB_SCAN, 1024>>>();
    scan2_kernel<<<1, 32>>>();
    scan3_kernel<<<gNode, TB>>>();
    fill_kernel<<<gEdge, TB>>>(ei);

    // ---- layer 1 ----
    gemm_kernel<256><<<gGemm, TB>>>(x, W1, d_gh, NN);
    scores_kernel<<<gWarpNode, TB>>>(d_gh, as1, ad1);
    aggregate_kernel<false><<<gWarpNode, TB>>>(d_gh, b1, d_ghl,
                                               nullptr, nullptr, nullptr, nullptr, nullptr);

    // ---- layer 2 ----
    gemm_kernel<64><<<gGemm, TB>>>(d_ghl, W2, d_gh, NN);
    scores_kernel<<<gWarpNode, TB>>>(d_gh, as2, ad2);
    aggregate_kernel<true><<<gWarpNode, TB>>>(d_gh, b2, nullptr,
                                              Wf, bf, Ws, bs, out);
}

// round 3
// speedup vs baseline: 2.2077x; 1.1230x over previous
#include <cuda_runtime.h>
#include <cuda_bf16.h>

#define NN 100000
#define NE 1600000
#define HID 64
#define NEG_SLOPE 0.2f
#define NB_SCAN 98          // ceil(NN/1024)

// ---------------- scratch (device globals) ----------------
__device__ float g_h[NN * HID];     // pre-attention features of current layer
__device__ float g_hl[NN * HID];    // layer-1 output (layer-2 input)
__device__ float g_as[NN];
__device__ float g_ad[NN];
__device__ int   g_cnt[NN];
__device__ int   g_cur[NN];
__device__ int   g_rowptr[NN + 1];
__device__ int   g_bsum[NB_SCAN];
__device__ int   g_csr[NE];

// ---------------- f32x2 helpers ----------------
__device__ __forceinline__ unsigned long long ffma2(unsigned long long a,
                                                    unsigned long long b,
                                                    unsigned long long c) {
    unsigned long long d;
    asm("fma.rn.f32x2 %0,%1,%2,%3;" : "=l"(d) : "l"(a), "l"(b), "l"(c));
    return d;
}
__device__ __forceinline__ unsigned long long dup2(float x) {
    unsigned long long r;
    asm("mov.b64 %0,{%1,%1};" : "=l"(r) : "f"(x));
    return r;
}
__device__ __forceinline__ float2 unpk(unsigned long long p) {
    float2 r;
    asm("mov.b64 {%0,%1},%2;" : "=f"(r.x), "=f"(r.y) : "l"(p));
    return r;
}
__device__ __forceinline__ float lrelu(float v) {
    return (v > 0.0f) ? v : NEG_SLOPE * v;
}

// ================= CSR build =================
__global__ void zero_kernel() {
    int i = blockIdx.x * blockDim.x + threadIdx.x;
    if (i < NN) { g_cnt[i] = 0; g_cur[i] = 0; }
}
__global__ void hist_kernel(const int* __restrict__ ei) {
    int e = blockIdx.x * blockDim.x + threadIdx.x;
    if (e >= NE) return;
    atomicAdd(&g_cnt[ei[NE + e]], 1);
}
// shuffle-based block scan (1024 threads)
__global__ void scan1_kernel() {
    __shared__ int wsum[32];
    int i = blockIdx.x * 1024 + threadIdx.x;
    int lane = threadIdx.x & 31;
    int wid = threadIdx.x >> 5;
    int v = (i < NN) ? g_cnt[i] : 0;
    int x = v;
    #pragma unroll
    for (int o = 1; o < 32; o <<= 1) {
        int t = __shfl_up_sync(0xffffffffu, x, o);
        if (lane >= o) x += t;
    }
    if (lane == 31) wsum[wid] = x;
    __syncthreads();
    if (wid == 0) {
        int y = wsum[lane];
        #pragma unroll
        for (int o = 1; o < 32; o <<= 1) {
            int t = __shfl_up_sync(0xffffffffu, y, o);
            if (lane >= o) y += t;
        }
        wsum[lane] = y;
    }
    __syncthreads();
    int add = wid ? wsum[wid - 1] : 0;
    x += add;
    if (i < NN) g_rowptr[i] = x - v;   // exclusive
    if (threadIdx.x == 1023) g_bsum[blockIdx.x] = x;
}
__global__ void scan2_kernel() {   // 1 block, 128 threads over 98 block sums
    __shared__ int s[128];
    int i = threadIdx.x;
    int v = (i < NB_SCAN) ? g_bsum[i] : 0;
    s[i] = v;
    __syncthreads();
    #pragma unroll
    for (int o = 1; o < 128; o <<= 1) {
        int t = (i >= o) ? s[i - o] : 0;
        __syncthreads();
        s[i] += t;
        __syncthreads();
    }
    if (i < NB_SCAN) g_bsum[i] = s[i] - v;   // exclusive
    if (i == NB_SCAN - 1) g_rowptr[NN] = s[i];
}
__global__ void scan3_kernel() {
    int i = blockIdx.x * blockDim.x + threadIdx.x;
    if (i < NN) g_rowptr[i] += g_bsum[i >> 10];
}
__global__ void fill_kernel(const int* __restrict__ ei) {
    int e = blockIdx.x * blockDim.x + threadIdx.x;
    if (e >= NE) return;
    int s = ei[e], d = ei[NE + e];
    int pos = g_rowptr[d] + atomicAdd(&g_cur[d], 1);
    g_csr[pos] = s;
}

// ================= tiled GEMM (128x64 per block, FFMA2) + fused attention scores ====
template<int K>
__global__ void __launch_bounds__(256) gemm_kernel(const float* __restrict__ X,
                                                   const float* __restrict__ W,
                                                   const float* __restrict__ a_s,
                                                   const float* __restrict__ a_d,
                                                   float* __restrict__ H, int nrows) {
    __shared__ float xs[16][132];   // transposed x chunk: xs[kk][row]
    __shared__ float ws[16][64];    // w chunk: ws[kk][col]
    int t = threadIdx.x;
    int rowblk = blockIdx.x * 128;

    int col4 = (t & 15) * 4;        // 4 consecutive output cols
    int r0   = (t >> 4) * 8;        // 8 consecutive rows (4 packed pairs)

    unsigned long long acc[4][4];
    #pragma unroll
    for (int i = 0; i < 4; i++)
        #pragma unroll
        for (int j = 0; j < 4; j++) acc[i][j] = 0ull;

    int lrow = t >> 1;
    int lk   = (t & 1) * 8;
    int grow = rowblk + lrow; if (grow >= nrows) grow = nrows - 1;
    const float4* xsrc = (const float4*)(X + (size_t)grow * K);

    for (int k0 = 0; k0 < K; k0 += 16) {
        float4 v0 = xsrc[(k0 + lk) >> 2];
        float4 v1 = xsrc[(k0 + lk + 4) >> 2];
        float4 wv4 = ((const float4*)(W + k0 * 64))[t];
        __syncthreads();
        xs[lk + 0][lrow] = v0.x; xs[lk + 1][lrow] = v0.y;
        xs[lk + 2][lrow] = v0.z; xs[lk + 3][lrow] = v0.w;
        xs[lk + 4][lrow] = v1.x; xs[lk + 5][lrow] = v1.y;
        xs[lk + 6][lrow] = v1.z; xs[lk + 7][lrow] = v1.w;
        ((float4*)ws)[t] = wv4;
        __syncthreads();
        #pragma unroll
        for (int kk = 0; kk < 16; kk++) {
            float4 wv = *(const float4*)&ws[kk][col4];
            unsigned long long wd0 = dup2(wv.x), wd1 = dup2(wv.y),
                               wd2 = dup2(wv.z), wd3 = dup2(wv.w);
            #pragma unroll
            for (int i = 0; i < 4; i++) {
                unsigned long long xp =
                    *(const unsigned long long*)&xs[kk][r0 + 2 * i];
                acc[i][0] = ffma2(xp, wd0, acc[i][0]);
                acc[i][1] = ffma2(xp, wd1, acc[i][1]);
                acc[i][2] = ffma2(xp, wd2, acc[i][2]);
                acc[i][3] = ffma2(xp, wd3, acc[i][3]);
            }
        }
    }

    // unpack + store H
    int orow = rowblk + r0;
    float2 c[4][4];
    #pragma unroll
    for (int i = 0; i < 4; i++) {
        #pragma unroll
        for (int j = 0; j < 4; j++) c[i][j] = unpk(acc[i][j]);
        int rlo = orow + 2 * i, rhi = rlo + 1;
        if (rlo < nrows)
            *(float4*)(H + (size_t)rlo * 64 + col4) =
                make_float4(c[i][0].x, c[i][1].x, c[i][2].x, c[i][3].x);
        if (rhi < nrows)
            *(float4*)(H + (size_t)rhi * 64 + col4) =
                make_float4(c[i][0].y, c[i][1].y, c[i][2].y, c[i][3].y);
    }

    // fused attention scores: per-row dot with a_src / a_dst
    float4 asv = *(const float4*)(a_s + col4);
    float4 adv = *(const float4*)(a_d + col4);
    float ps[8], pd[8];   // 8 rows owned by this thread
    #pragma unroll
    for (int i = 0; i < 4; i++) {
        ps[2*i]   = c[i][0].x*asv.x + c[i][1].x*asv.y + c[i][2].x*asv.z + c[i][3].x*asv.w;
        ps[2*i+1] = c[i][0].y*asv.x + c[i][1].y*asv.y + c[i][2].y*asv.z + c[i][3].y*asv.w;
        pd[2*i]   = c[i][0].x*adv.x + c[i][1].x*adv.y + c[i][2].x*adv.z + c[i][3].x*adv.w;
        pd[2*i+1] = c[i][0].y*adv.x + c[i][1].y*adv.y + c[i][2].y*adv.z + c[i][3].y*adv.w;
    }
    // reduce across the 16 threads (same rows) — width-16 shuffles
    #pragma unroll
    for (int r = 0; r < 8; r++) {
        #pragma unroll
        for (int o = 8; o; o >>= 1) {
            ps[r] += __shfl_down_sync(0xffffffffu, ps[r], o, 16);
            pd[r] += __shfl_down_sync(0xffffffffu, pd[r], o, 16);
        }
    }
    if ((t & 15) == 0) {
        #pragma unroll
        for (int r = 0; r < 8; r++) {
            int row = orow + r;
            if (row < nrows) { g_as[row] = ps[r]; g_ad[row] = pd[r]; }
        }
    }
}

// ================= fused aggregation: softmax + weighted gather + epilogue ===========
template<bool LAYER2>
__global__ void aggregate_kernel(const float* __restrict__ h,
                                 const float* __restrict__ bias,
                                 float* __restrict__ dsth,
                                 const float* __restrict__ Wf, const float* __restrict__ bf,
                                 const float* __restrict__ Ws, const float* __restrict__ bs,
                                 float* __restrict__ out) {
    int n = (blockIdx.x * blockDim.x + threadIdx.x) >> 5;
    int lane = threadIdx.x & 31;
    if (n >= NN) return;
    int base = g_rowptr[n], end = g_rowptr[n + 1];
    float adn = g_ad[n];
    float eself = lrelu(g_as[n] + adn);

    // pass 1: segment max (lanes strided over edges)
    float m = eself;
    for (int j = base + lane; j < end; j += 32)
        m = fmaxf(m, lrelu(g_as[g_csr[j]] + adn));
    #pragma unroll
    for (int o = 16; o; o >>= 1)
        m = fmaxf(m, __shfl_xor_sync(0xffffffffu, m, o));

    // pass 2: exp-weighted gather, 4 edges in flight
    int c0 = 2 * lane;
    float wself = __expf(eself - m);
    float den = wself;
    float2 hv = *(const float2*)(h + (size_t)n * HID + c0);
    float accx = wself * hv.x, accy = wself * hv.y;

    int j = base;
    for (; j + 4 <= end; j += 4) {
        int s0 = g_csr[j], s1 = g_csr[j+1], s2 = g_csr[j+2], s3 = g_csr[j+3];
        float a0 = g_as[s0], a1 = g_as[s1], a2 = g_as[s2], a3 = g_as[s3];
        float2 h0 = *(const float2*)(h + (size_t)s0 * HID + c0);
        float2 h1 = *(const float2*)(h + (size_t)s1 * HID + c0);
        float2 h2 = *(const float2*)(h + (size_t)s2 * HID + c0);
        float2 h3 = *(const float2*)(h + (size_t)s3 * HID + c0);
        float w0 = __expf(lrelu(a0 + adn) - m);
        float w1 = __expf(lrelu(a1 + adn) - m);
        float w2 = __expf(lrelu(a2 + adn) - m);
        float w3 = __expf(lrelu(a3 + adn) - m);
        den += (w0 + w1) + (w2 + w3);
        accx = fmaf(w0, h0.x, accx); accy = fmaf(w0, h0.y, accy);
        accx = fmaf(w1, h1.x, accx); accy = fmaf(w1, h1.y, accy);
        accx = fmaf(w2, h2.x, accx); accy = fmaf(w2, h2.y, accy);
        accx = fmaf(w3, h3.x, accx); accy = fmaf(w3, h3.y, accy);
    }
    for (; j < end; j++) {
        int s = g_csr[j];
        float w = __expf(lrelu(g_as[s] + adn) - m);
        float2 hs = *(const float2*)(h + (size_t)s * HID + c0);
        den += w;
        accx = fmaf(w, hs.x, accx);
        accy = fmaf(w, hs.y, accy);
    }

    float inv = 1.0f / den;
    float h0 = accx * inv + bias[c0];
    float h1 = accy * inv + bias[c0 + 1];
    h0 = (h0 > 0.0f) ? h0 : 0.0f;
    h1 = (h1 > 0.0f) ? h1 : 0.0f;

    if (!LAYER2) {
        *(float2*)(dsth + (size_t)n * HID + c0) = make_float2(h0, h1);
    } else {
        float acc[10];
        #pragma unroll
        for (int jj = 0; jj < 3; jj++)
            acc[jj] = h0 * Wf[c0 * 3 + jj] + h1 * Wf[(c0 + 1) * 3 + jj];
        #pragma unroll
        for (int jj = 0; jj < 7; jj++)
            acc[3 + jj] = h0 * Ws[c0 * 7 + jj] + h1 * Ws[(c0 + 1) * 7 + jj];
        #pragma unroll
        for (int jj = 0; jj < 10; jj++) {
            #pragma unroll
            for (int o = 16; o; o >>= 1)
                acc[jj] += __shfl_down_sync(0xffffffffu, acc[jj], o);
        }
        if (lane == 0) {
            #pragma unroll
            for (int jj = 0; jj < 3; jj++) out[(size_t)n * 3 + jj] = acc[jj] + bf[jj];
            #pragma unroll
            for (int jj = 0; jj < 7; jj++)
                out[(size_t)NN * 3 + (size_t)n * 7 + jj] = acc[3 + jj] + bs[jj];
        }
    }
}

extern "C" void kernel_launch(void* const* d_in, const int* in_sizes, int n_in,
                              void* d_out, int out_size) {
    const float* x    = (const float*)d_in[0];
    const int*   ei   = (const int*)d_in[1];
    const float* W1   = (const float*)d_in[2];
    const float* as1  = (const float*)d_in[3];
    const float* ad1  = (const float*)d_in[4];
    const float* b1   = (const float*)d_in[5];
    const float* W2   = (const float*)d_in[6];
    const float* as2  = (const float*)d_in[7];
    const float* ad2  = (const float*)d_in[8];
    const float* b2   = (const float*)d_in[9];
    const float* Wf   = (const float*)d_in[10];
    const float* bf   = (const float*)d_in[11];
    const float* Ws   = (const float*)d_in[12];
    const float* bs   = (const float*)d_in[13];
    float* out = (float*)d_out;

    float* d_gh;  cudaGetSymbolAddress((void**)&d_gh,  g_h);
    float* d_ghl; cudaGetSymbolAddress((void**)&d_ghl, g_hl);

    const int TB = 256;
    dim3 gNode((NN + TB - 1) / TB);
    dim3 gEdge((NE + TB - 1) / TB);
    dim3 gGemm((NN + 127) / 128);
    dim3 gWarpNode(((size_t)NN * 32 + TB - 1) / TB);

    // ---- CSR build (shared by both layers) ----
    zero_kernel<<<gNode, TB>>>();
    hist_kernel<<<gEdge, TB>>>(ei);
    scan1_kernel<<<NB_SCAN, 1024>>>();
    scan2_kernel<<<1, 128>>>();
    scan3_kernel<<<gNode, TB>>>();
    fill_kernel<<<gEdge, TB>>>(ei);

    // ---- layer 1 ----
    gemm_kernel<256><<<gGemm, TB>>>(x, W1, as1, ad1, d_gh, NN);
    aggregate_kernel<false><<<gWarpNode, TB>>>(d_gh, b1, d_ghl,
                                               nullptr, nullptr, nullptr, nullptr, nullptr);

    // ---- layer 2 ----
    gemm_kernel<64><<<gGemm, TB>>>(d_ghl, W2, as2, ad2, d_gh, NN);
    aggregate_kernel<true><<<gWarpNode, TB>>>(d_gh, b2, nullptr,
                                              Wf, bf, Ws, bs, out);
}